// round 12
// baseline (speedup 1.0000x reference)
#include <cuda_runtime.h>

// SceneEngine: closed-form subset-sum factorization.
//   Σ over non-empty subsets of exp(Σ_s exist[s,bit_s]) = Π_s(e0+e1) − Π_s e0
//   number_prob  -> elementary symmetric polynomial DP on Π_s(e0 + t·e1)
//   attr prob[d] -> (Π_s(e0 + e1·exp(a[s,d])) − Π_s e0) / Z
//
// R12: 256 blocks (one b each) × 224 threads (7 warps). Attr warps cover
// 8 pairs, lane=(k<<2)|(h<<1)|g: h splits dims, g splits SLOTS (s 0-4 / 5-8)
// — partial products combine via shfl-mul, dim halves via shfl-add.
// Per-lane chain <= ~30 loads / ~35 exps. Barrier-free, direct GMEM.
//   w0: exist_prob (h=1) + symmetric DP + number (h=0)
//   w1/w2: type k0-7 / k8-15   w3/w4: size   w5/w6: color
// Rule/norm live in the k0-7 warp of each attr (whole-warp min).

constexpr int NS = 9;

constexpr int OFF_EXIST  = 0;
constexpr int OFF_NUM    = 73728;
constexpr int OFF_TYPE   = 110592;
constexpr int OFF_NTYPE  = 135168;
constexpr int OFF_RTYPE  = 145408;
constexpr int OFF_SIZE   = 145664;
constexpr int OFF_NSIZE  = 174336;
constexpr int OFF_RSIZE  = 186624;
constexpr int OFF_COLOR  = 186880;
constexpr int OFF_NCOLOR = 231936;
constexpr int OFF_RCOLOR = 252416;

__device__ __forceinline__ float warp_min(float v)
{
#pragma unroll
    for (int off = 16; off >= 1; off >>= 1)
        v = fminf(v, __shfl_xor_sync(0xFFFFFFFFu, v, off));
    return v;
}

// attr role with slot+dim split. Warp covers 8 pairs (k = kbase + lane>>2).
// lane bits: h = (lane>>1)&1 selects dims [0,H0) or [H0,D);
//            g = lane&1 selects slots s in [0,5) or [5,9).
// LOWK warps (k = 0..7) also write norm and rule.
template <int D, int H0, int MAXND, bool LOWK>
__device__ __forceinline__ void attr_sg(
    const float* __restrict__ attr,
    const float* __restrict__ exist,
    int b, int kbase, int lane,
    float* __restrict__ out,
    int off_prob, int off_norm, int off_rule)
{
    int k    = (lane >> 2) + kbase;
    int h    = (lane >> 1) & 1;
    int g    = lane & 1;
    int pair = b * 16 + k;
    int nd    = h ? (D - H0) : H0;
    int dbase = h ? H0 : 0;
    int s0    = g ? 5 : 0;
    int ns    = g ? 4 : 5;

    // ---- partial products over this lane's slot range ----
    const float2* __restrict__ er =
        (const float2*)(exist + (size_t)pair * 18 + 2 * s0);
    const float* __restrict__ a =
        attr + (size_t)pair * NS * D + s0 * D + dbase;

    float pp[MAXND];
#pragma unroll
    for (int j = 0; j < MAXND; j++) pp[j] = 1.0f;
    float pS0 = 1.0f, pZp = 1.0f;

#pragma unroll
    for (int s = 0; s < 5; s++) {
        if (s < ns) {
            float2 e = er[s];
            float e0 = __expf(e.x);
            float e1 = __expf(e.y);
            pS0 *= e0;
            pZp *= (e0 + e1);
#pragma unroll
            for (int j = 0; j < MAXND; j++) {
                if (j < nd)
                    pp[j] *= fmaf(e1, __expf(a[s * D + j]), e0);
            }
        }
    }

    // ---- combine slot halves (xor 1): products multiply ----
    float S0 = pS0 * __shfl_xor_sync(0xFFFFFFFFu, pS0, 1);
    float Zp = pZp * __shfl_xor_sync(0xFFFFFFFFu, pZp, 1);
    float p[MAXND];
#pragma unroll
    for (int j = 0; j < MAXND; j++)
        p[j] = pp[j] * __shfl_xor_sync(0xFFFFFFFFu, pp[j], 1);

    float invZ = __fdividef(1.0f, Zp - S0);
    float part = 0.0f;
#pragma unroll
    for (int j = 0; j < MAXND; j++) {
        if (j < nd) {
            p[j] = (p[j] - S0) * invZ;
            part += p[j];
        }
    }
    // ---- combine dim halves (xor 2): sums add ----
    float sum = part + __shfl_xor_sync(0xFFFFFFFFu, part, 2);
    float nic = fminf(sum, 1.0f);

    if (g == 0) {
        float* __restrict__ op = out + off_prob + (size_t)pair * (D + 1) + dbase;
#pragma unroll
        for (int j = 0; j < MAXND; j++)
            if (j < nd) op[j] = p[j];
        if (h) op[nd] = 1.0f - nic;      // element D (dbase + nd == D)

        if (LOWK) {
            float inv = __fdividef(1.0f, sum);
            float* __restrict__ on = out + off_norm + (size_t)(b * 8 + k) * D + dbase;
#pragma unroll
            for (int j = 0; j < MAXND; j++)
                if (j < nd) on[j] = p[j] * inv;
        }
    }

    if (LOWK) {
        float v = warp_min(nic);         // min over the warp's 8 k's (= k<8)
        if (lane == 0) out[off_rule + b] = v;
    }
}

__global__ __launch_bounds__(224)
void scene_engine_kernel(const float* __restrict__ exist,
                         const float* __restrict__ typ,
                         const float* __restrict__ siz,
                         const float* __restrict__ col,
                         float* __restrict__ out)
{
    int t = threadIdx.x;
    int w = t >> 5;
    int lane = t & 31;
    int b = blockIdx.x;

    if (w == 0) {
        // lane = (p<<1)|h : h=1 writes exist_prob, h=0 does DP + number.
        int p = lane >> 1;
        int h = lane & 1;
        int pair = b * 16 + p;

        const float2* __restrict__ er = (const float2*)(exist + (size_t)pair * 18);
        float e0[NS], e1[NS];
#pragma unroll
        for (int s = 0; s < NS; s++) {
            float2 e = er[s];
            e0[s] = __expf(e.x);
            e1[s] = __expf(e.y);
        }

        if (h) {
            float2* __restrict__ oex = (float2*)(out + OFF_EXIST + (size_t)pair * 18);
#pragma unroll
            for (int s = 0; s < NS; s++)
                oex[s] = make_float2(e0[s], e1[s]);
        } else {
            // elementary symmetric polynomial DP
            float c[NS + 1];
            c[0] = 1.0f;
#pragma unroll
            for (int i = 1; i <= NS; i++) c[i] = 0.0f;
#pragma unroll
            for (int s = 0; s < NS; s++) {
#pragma unroll
                for (int j = NS; j >= 1; j--)
                    c[j] = fmaf(c[j], e0[s], c[j - 1] * e1[s]);
                c[0] *= e0[s];
            }
            float Z = 0.0f;
#pragma unroll
            for (int j = 1; j <= NS; j++) Z += c[j];
            float invZ = __fdividef(1.0f, Z);

            float* __restrict__ onum = out + OFF_NUM + (size_t)pair * NS;
#pragma unroll
            for (int n = 0; n < NS; n++) onum[n] = c[n + 1] * invZ;
        }
    } else if (w == 1) {
        attr_sg<5, 3, 3, true >(typ, exist, b, 0, lane, out, OFF_TYPE, OFF_NTYPE, OFF_RTYPE);
    } else if (w == 2) {
        attr_sg<5, 3, 3, false>(typ, exist, b, 8, lane, out, OFF_TYPE, OFF_NTYPE, OFF_RTYPE);
    } else if (w == 3) {
        attr_sg<6, 3, 3, true >(siz, exist, b, 0, lane, out, OFF_SIZE, OFF_NSIZE, OFF_RSIZE);
    } else if (w == 4) {
        attr_sg<6, 3, 3, false>(siz, exist, b, 8, lane, out, OFF_SIZE, OFF_NSIZE, OFF_RSIZE);
    } else if (w == 5) {
        attr_sg<10, 5, 5, true >(col, exist, b, 0, lane, out, OFF_COLOR, OFF_NCOLOR, OFF_RCOLOR);
    } else {
        attr_sg<10, 5, 5, false>(col, exist, b, 8, lane, out, OFF_COLOR, OFF_NCOLOR, OFF_RCOLOR);
    }
}

extern "C" void kernel_launch(void* const* d_in, const int* in_sizes, int n_in,
                              void* d_out, int out_size)
{
    const float* exist = (const float*)d_in[0];
    const float* typ   = (const float*)d_in[1];
    const float* siz   = (const float*)d_in[2];
    const float* col   = (const float*)d_in[3];
    float* out = (float*)d_out;

    // 256 blocks (one b each) × 224 threads (7 role warps).
    scene_engine_kernel<<<256, 224>>>(exist, typ, siz, col, out);
}

// round 13
// speedup vs baseline: 1.0139x; 1.0139x over previous
#include <cuda_runtime.h>

// SceneEngine: closed-form subset-sum factorization.
//   Σ over non-empty subsets of exp(Σ_s exist[s,bit_s]) = Π_s(e0+e1) − Π_s e0
//   number_prob  -> elementary symmetric polynomial DP on Π_s(e0 + t·e1)
//   attr prob[d] -> (Π_s(e0 + e1·exp(a[s,d])) − Π_s e0) / Z
//
// R13: R11 structure (best: 256 blocks = one b each, 160 threads, 5 role
// warps, barrier-free direct GMEM) + register-greedy compilation:
//   * __launch_bounds__(160, 1): lift ptxas's occupancy-driven register
//     clamp (regs were 32-48 across R7-R12, capping MLP at ~8-10 loads)
//   * explicit front-load of all inputs into register arrays (phase 1),
//     then pure compute (phase 2) -> one exposed memory round-trip
//   * float2 exist loads (9 LDG.64 instead of 18 LDG.32)
//   w0: exist_prob + symmetric DP + number (16 active lanes)
//   w1: type  D=5, lane=(k<<1)|h, dims 3+2
//   w2: size  D=6, lane=(k<<1)|h, dims 3+3
//   w3: color D=10, k=0-7,  lane=(k<<2)|q, dims 3+3+3+1; norm+rule here
//   w4: color k=8-15, prob only

constexpr int NS = 9;

constexpr int OFF_EXIST  = 0;
constexpr int OFF_NUM    = 73728;
constexpr int OFF_TYPE   = 110592;
constexpr int OFF_NTYPE  = 135168;
constexpr int OFF_RTYPE  = 145408;
constexpr int OFF_SIZE   = 145664;
constexpr int OFF_NSIZE  = 174336;
constexpr int OFF_RSIZE  = 186624;
constexpr int OFF_COLOR  = 186880;
constexpr int OFF_NCOLOR = 231936;
constexpr int OFF_RCOLOR = 252416;

#define BIGF 3.402823466e+38f

__device__ __forceinline__ float warp_min(float v)
{
#pragma unroll
    for (int off = 16; off >= 1; off >>= 1)
        v = fminf(v, __shfl_xor_sync(0xFFFFFFFFu, v, off));
    return v;
}

// type/size role: warp covers 16 pairs, lane=(k<<1)|h; h=0 -> dims [0,H0),
// h=1 -> dims [H0,D). norm for k<8; rule = min over k<8.
template <int D, int H0>
__device__ __forceinline__ void attr_split(
    const float* __restrict__ attr,
    const float* __restrict__ exist,
    int b, int lane,
    float* __restrict__ out,
    int off_prob, int off_norm, int off_rule)
{
    int k = lane >> 1;
    int h = lane & 1;
    int pair = b * 16 + k;
    int nd    = h ? (D - H0) : H0;       // <= 3
    int dbase = h ? H0 : 0;

    // ---- phase 1: front-load everything ----
    float2 exr[NS];
    {
        const float2* __restrict__ er = (const float2*)(exist + (size_t)pair * 18);
#pragma unroll
        for (int s = 0; s < NS; s++) exr[s] = er[s];
    }
    float ar[NS * 3];
    {
        const float* __restrict__ a = attr + (size_t)pair * NS * D + dbase;
#pragma unroll
        for (int s = 0; s < NS; s++)
#pragma unroll
            for (int j = 0; j < 3; j++)
                ar[s * 3 + j] = (j < nd) ? a[s * D + j] : 0.0f;
    }

    // ---- phase 2: pure register compute ----
    float e0[NS], e1[NS];
#pragma unroll
    for (int s = 0; s < NS; s++) {
        e0[s] = __expf(exr[s].x);
        e1[s] = __expf(exr[s].y);
    }
    float S0 = 1.0f, Zp = 1.0f;
#pragma unroll
    for (int s = 0; s < NS; s++) { S0 *= e0[s]; Zp *= (e0[s] + e1[s]); }
    float invZ = __fdividef(1.0f, Zp - S0);

    float p[3];
#pragma unroll
    for (int j = 0; j < 3; j++) p[j] = 1.0f;
#pragma unroll
    for (int s = 0; s < NS; s++) {
#pragma unroll
        for (int j = 0; j < 3; j++) {
            if (j < nd)
                p[j] *= fmaf(e1[s], __expf(ar[s * 3 + j]), e0[s]);
        }
    }

    float part = 0.0f;
#pragma unroll
    for (int j = 0; j < 3; j++) {
        if (j < nd) {
            p[j] = (p[j] - S0) * invZ;
            part += p[j];
        }
    }
    float sum = part + __shfl_xor_sync(0xFFFFFFFFu, part, 1);
    float nic = fminf(sum, 1.0f);

    float* __restrict__ op = out + off_prob + (size_t)pair * (D + 1) + dbase;
#pragma unroll
    for (int j = 0; j < 3; j++)
        if (j < nd) op[j] = p[j];
    if (h) op[D - dbase] = 1.0f - nic;   // element D

    if (k < 8) {
        float inv = __fdividef(1.0f, sum);
        float* __restrict__ on = out + off_norm + (size_t)(b * 8 + k) * D + dbase;
#pragma unroll
        for (int j = 0; j < 3; j++)
            if (j < nd) on[j] = p[j] * inv;
    }

    float v = (k < 8) ? nic : BIGF;
    v = warp_min(v);
    if (lane == 0) out[off_rule + b] = v;
}

// color role: warp covers 8 pairs, lane=(k_loc<<2)|q; q<3 -> 3 dims at q*3,
// q==3 -> dim 9. LOWK warp (k=0-7) also writes norm + rule.
template <bool LOWK>
__device__ __forceinline__ void color_q(
    const float* __restrict__ col,
    const float* __restrict__ exist,
    int b, int lane,
    float* __restrict__ out)
{
    int q = lane & 3;
    int k = (lane >> 2) + (LOWK ? 0 : 8);
    int pair = b * 16 + k;
    int nd    = (q == 3) ? 1 : 3;
    int dbase = q * 3;

    // ---- phase 1: front-load ----
    float2 exr[NS];
    {
        const float2* __restrict__ er = (const float2*)(exist + (size_t)pair * 18);
#pragma unroll
        for (int s = 0; s < NS; s++) exr[s] = er[s];
    }
    float ar[NS * 3];
    {
        const float* __restrict__ a = col + (size_t)pair * 90 + dbase;
#pragma unroll
        for (int s = 0; s < NS; s++)
#pragma unroll
            for (int j = 0; j < 3; j++)
                ar[s * 3 + j] = (j < nd) ? a[s * 10 + j] : 0.0f;
    }

    // ---- phase 2: compute ----
    float e0[NS], e1[NS];
#pragma unroll
    for (int s = 0; s < NS; s++) {
        e0[s] = __expf(exr[s].x);
        e1[s] = __expf(exr[s].y);
    }
    float S0 = 1.0f, Zp = 1.0f;
#pragma unroll
    for (int s = 0; s < NS; s++) { S0 *= e0[s]; Zp *= (e0[s] + e1[s]); }
    float invZ = __fdividef(1.0f, Zp - S0);

    float p[3];
#pragma unroll
    for (int j = 0; j < 3; j++) p[j] = 1.0f;
#pragma unroll
    for (int s = 0; s < NS; s++) {
#pragma unroll
        for (int j = 0; j < 3; j++) {
            if (j < nd)
                p[j] *= fmaf(e1[s], __expf(ar[s * 3 + j]), e0[s]);
        }
    }

    float part = 0.0f;
#pragma unroll
    for (int j = 0; j < 3; j++) {
        if (j < nd) {
            p[j] = (p[j] - S0) * invZ;
            part += p[j];
        }
    }
    // sum across the 4 q-lanes of this pair
    part += __shfl_xor_sync(0xFFFFFFFFu, part, 1);
    part += __shfl_xor_sync(0xFFFFFFFFu, part, 2);
    float sum = part;
    float nic = fminf(sum, 1.0f);

    float* __restrict__ op = out + OFF_COLOR + (size_t)pair * 11 + dbase;
#pragma unroll
    for (int j = 0; j < 3; j++)
        if (j < nd) op[j] = p[j];
    if (q == 3) op[1] = 1.0f - nic;      // element 10 (= dbase 9 + 1)

    if (LOWK) {
        float inv = __fdividef(1.0f, sum);
        float* __restrict__ on = out + OFF_NCOLOR + (size_t)(b * 8 + k) * 10 + dbase;
#pragma unroll
        for (int j = 0; j < 3; j++)
            if (j < nd) on[j] = p[j] * inv;

        float v = warp_min(nic);         // min over the 8 pairs (k<8)
        if (lane == 0) out[OFF_RCOLOR + b] = v;
    }
}

__global__ __launch_bounds__(160, 1)
void scene_engine_kernel(const float* __restrict__ exist,
                         const float* __restrict__ typ,
                         const float* __restrict__ siz,
                         const float* __restrict__ col,
                         float* __restrict__ out)
{
    int t = threadIdx.x;
    int w = t >> 5;
    int lane = t & 31;
    int b = blockIdx.x;

    if (w == 0) {
        if (lane < 16) {
            int pair = b * 16 + lane;
            // phase 1: front-load exist row (float2)
            float2 exr[NS];
            {
                const float2* __restrict__ er = (const float2*)(exist + (size_t)pair * 18);
#pragma unroll
                for (int s = 0; s < NS; s++) exr[s] = er[s];
            }
            // phase 2
            float e0[NS], e1[NS];
#pragma unroll
            for (int s = 0; s < NS; s++) {
                e0[s] = __expf(exr[s].x);
                e1[s] = __expf(exr[s].y);
            }

            float2* __restrict__ oex = (float2*)(out + OFF_EXIST + (size_t)pair * 18);
#pragma unroll
            for (int s = 0; s < NS; s++)
                oex[s] = make_float2(e0[s], e1[s]);

            // elementary symmetric polynomial DP
            float c[NS + 1];
            c[0] = 1.0f;
#pragma unroll
            for (int i = 1; i <= NS; i++) c[i] = 0.0f;
#pragma unroll
            for (int s = 0; s < NS; s++) {
#pragma unroll
                for (int j = NS; j >= 1; j--)
                    c[j] = fmaf(c[j], e0[s], c[j - 1] * e1[s]);
                c[0] *= e0[s];
            }
            float Z = 0.0f;
#pragma unroll
            for (int j = 1; j <= NS; j++) Z += c[j];
            float invZ = __fdividef(1.0f, Z);

            float* __restrict__ onum = out + OFF_NUM + (size_t)pair * NS;
#pragma unroll
            for (int n = 0; n < NS; n++) onum[n] = c[n + 1] * invZ;
        }
    } else if (w == 1) {
        attr_split<5, 3>(typ, exist, b, lane, out, OFF_TYPE, OFF_NTYPE, OFF_RTYPE);
    } else if (w == 2) {
        attr_split<6, 3>(siz, exist, b, lane, out, OFF_SIZE, OFF_NSIZE, OFF_RSIZE);
    } else if (w == 3) {
        color_q<true>(col, exist, b, lane, out);
    } else {
        color_q<false>(col, exist, b, lane, out);
    }
}

extern "C" void kernel_launch(void* const* d_in, const int* in_sizes, int n_in,
                              void* d_out, int out_size)
{
    const float* exist = (const float*)d_in[0];
    const float* typ   = (const float*)d_in[1];
    const float* siz   = (const float*)d_in[2];
    const float* col   = (const float*)d_in[3];
    float* out = (float*)d_out;

    // 256 blocks (one b each) × 160 threads: 2 CTAs/SM resident, 10 warps/SM.
    scene_engine_kernel<<<256, 160>>>(exist, typ, siz, col, out);
}

// round 15
// speedup vs baseline: 1.0735x; 1.0588x over previous
#include <cuda_runtime.h>

// SceneEngine: closed-form subset-sum factorization.
//   Σ over non-empty subsets of exp(Σ_s exist[s,bit_s]) = Π_s(e0+e1) − Π_s e0
//   number_prob  -> elementary symmetric polynomial DP on Π_s(e0 + t·e1)
//   attr prob[d] -> (Π_s(e0 + e1·exp(a[s,d])) − Π_s e0) / Z
//
// R14 (re-bench; prior run was an infra failure): single-wave layout.
// 128 blocks × 320 threads (10 warps) — each block handles TWO b's with two
// copies of R11's proven 5-warp role set. Eliminates the 256-CTA / 148-SM
// wave imbalance (108 SMs ran 2 CTAs). Per-warp code identical to R11.
// Barrier-free, direct GMEM.
//   per b: w+0: exist_prob + symmetric DP + number (16 active lanes)
//          w+1: type  D=5, lane=(k<<1)|h, dims 3+2
//          w+2: size  D=6, lane=(k<<1)|h, dims 3+3
//          w+3: color k=0-7,  lane=(k<<2)|q, dims 3+3+3+1; norm+rule
//          w+4: color k=8-15, prob only

constexpr int NS = 9;

constexpr int OFF_EXIST  = 0;
constexpr int OFF_NUM    = 73728;
constexpr int OFF_TYPE   = 110592;
constexpr int OFF_NTYPE  = 135168;
constexpr int OFF_RTYPE  = 145408;
constexpr int OFF_SIZE   = 145664;
constexpr int OFF_NSIZE  = 174336;
constexpr int OFF_RSIZE  = 186624;
constexpr int OFF_COLOR  = 186880;
constexpr int OFF_NCOLOR = 231936;
constexpr int OFF_RCOLOR = 252416;

#define BIGF 3.402823466e+38f

__device__ __forceinline__ void exp_exist(const float* __restrict__ r,
                                          float e0[NS], float e1[NS])
{
    const float2* __restrict__ er = (const float2*)r;
#pragma unroll
    for (int s = 0; s < NS; s++) {
        float2 e = er[s];
        e0[s] = __expf(e.x);
        e1[s] = __expf(e.y);
    }
}

__device__ __forceinline__ float warp_min(float v)
{
#pragma unroll
    for (int off = 16; off >= 1; off >>= 1)
        v = fminf(v, __shfl_xor_sync(0xFFFFFFFFu, v, off));
    return v;
}

// type/size role: warp covers 16 pairs, lane=(k<<1)|h; h=0 -> dims [0,H0),
// h=1 -> dims [H0,D). norm for k<8; rule = min over k<8.
template <int D, int H0>
__device__ __forceinline__ void attr_split(
    const float* __restrict__ attr,
    const float* __restrict__ exist,
    int b, int lane,
    float* __restrict__ out,
    int off_prob, int off_norm, int off_rule)
{
    int k = lane >> 1;
    int h = lane & 1;
    int pair = b * 16 + k;
    int nd    = h ? (D - H0) : H0;       // <= 3
    int dbase = h ? H0 : 0;

    float e0[NS], e1[NS];
    exp_exist(exist + (size_t)pair * 18, e0, e1);

    float S0 = 1.0f, Zp = 1.0f;
#pragma unroll
    for (int s = 0; s < NS; s++) { S0 *= e0[s]; Zp *= (e0[s] + e1[s]); }
    float invZ = __fdividef(1.0f, Zp - S0);

    const float* __restrict__ a = attr + (size_t)pair * NS * D + dbase;
    float p[3];
#pragma unroll
    for (int j = 0; j < 3; j++) p[j] = 1.0f;
#pragma unroll
    for (int s = 0; s < NS; s++) {
#pragma unroll
        for (int j = 0; j < 3; j++) {
            if (j < nd)
                p[j] *= fmaf(e1[s], __expf(a[s * D + j]), e0[s]);
        }
    }

    float part = 0.0f;
#pragma unroll
    for (int j = 0; j < 3; j++) {
        if (j < nd) {
            p[j] = (p[j] - S0) * invZ;
            part += p[j];
        }
    }
    float sum = part + __shfl_xor_sync(0xFFFFFFFFu, part, 1);
    float nic = fminf(sum, 1.0f);

    float* __restrict__ op = out + off_prob + (size_t)pair * (D + 1) + dbase;
#pragma unroll
    for (int j = 0; j < 3; j++)
        if (j < nd) op[j] = p[j];
    if (h) op[D - dbase] = 1.0f - nic;   // element D

    if (k < 8) {
        float inv = __fdividef(1.0f, sum);
        float* __restrict__ on = out + off_norm + (size_t)(b * 8 + k) * D + dbase;
#pragma unroll
        for (int j = 0; j < 3; j++)
            if (j < nd) on[j] = p[j] * inv;
    }

    float v = (k < 8) ? nic : BIGF;
    v = warp_min(v);
    if (lane == 0) out[off_rule + b] = v;
}

// color role: warp covers 8 pairs, lane=(k_loc<<2)|q; q<3 -> 3 dims at q*3,
// q==3 -> dim 9. LOWK warp (k=0-7) also writes norm + rule.
template <bool LOWK>
__device__ __forceinline__ void color_q(
    const float* __restrict__ col,
    const float* __restrict__ exist,
    int b, int lane,
    float* __restrict__ out)
{
    int q = lane & 3;
    int k = (lane >> 2) + (LOWK ? 0 : 8);
    int pair = b * 16 + k;
    int nd    = (q == 3) ? 1 : 3;
    int dbase = q * 3;

    float e0[NS], e1[NS];
    exp_exist(exist + (size_t)pair * 18, e0, e1);

    float S0 = 1.0f, Zp = 1.0f;
#pragma unroll
    for (int s = 0; s < NS; s++) { S0 *= e0[s]; Zp *= (e0[s] + e1[s]); }
    float invZ = __fdividef(1.0f, Zp - S0);

    const float* __restrict__ a = col + (size_t)pair * 90 + dbase;
    float p[3];
#pragma unroll
    for (int j = 0; j < 3; j++) p[j] = 1.0f;
#pragma unroll
    for (int s = 0; s < NS; s++) {
#pragma unroll
        for (int j = 0; j < 3; j++) {
            if (j < nd)
                p[j] *= fmaf(e1[s], __expf(a[s * 10 + j]), e0[s]);
        }
    }

    float part = 0.0f;
#pragma unroll
    for (int j = 0; j < 3; j++) {
        if (j < nd) {
            p[j] = (p[j] - S0) * invZ;
            part += p[j];
        }
    }
    // sum across the 4 q-lanes of this pair
    part += __shfl_xor_sync(0xFFFFFFFFu, part, 1);
    part += __shfl_xor_sync(0xFFFFFFFFu, part, 2);
    float sum = part;
    float nic = fminf(sum, 1.0f);

    float* __restrict__ op = out + OFF_COLOR + (size_t)pair * 11 + dbase;
#pragma unroll
    for (int j = 0; j < 3; j++)
        if (j < nd) op[j] = p[j];
    if (q == 3) op[1] = 1.0f - nic;      // element 10 (= dbase 9 + 1)

    if (LOWK) {
        float inv = __fdividef(1.0f, sum);
        float* __restrict__ on = out + OFF_NCOLOR + (size_t)(b * 8 + k) * 10 + dbase;
#pragma unroll
        for (int j = 0; j < 3; j++)
            if (j < nd) on[j] = p[j] * inv;

        float v = warp_min(nic);         // min over the 8 pairs (k<8)
        if (lane == 0) out[OFF_RCOLOR + b] = v;
    }
}

__global__ __launch_bounds__(320, 1)
void scene_engine_kernel(const float* __restrict__ exist,
                         const float* __restrict__ typ,
                         const float* __restrict__ siz,
                         const float* __restrict__ col,
                         float* __restrict__ out)
{
    int t = threadIdx.x;
    int w = t >> 5;
    int lane = t & 31;
    int b = blockIdx.x * 2 + (w >= 5 ? 1 : 0);   // two b's per block
    int role = (w >= 5) ? (w - 5) : w;

    if (role == 0) {
        if (lane < 16) {
            int pair = b * 16 + lane;
            float e0[NS], e1[NS];
            exp_exist(exist + (size_t)pair * 18, e0, e1);

            float2* __restrict__ oex = (float2*)(out + OFF_EXIST + (size_t)pair * 18);
#pragma unroll
            for (int s = 0; s < NS; s++)
                oex[s] = make_float2(e0[s], e1[s]);

            // elementary symmetric polynomial DP
            float c[NS + 1];
            c[0] = 1.0f;
#pragma unroll
            for (int i = 1; i <= NS; i++) c[i] = 0.0f;
#pragma unroll
            for (int s = 0; s < NS; s++) {
#pragma unroll
                for (int j = NS; j >= 1; j--)
                    c[j] = fmaf(c[j], e0[s], c[j - 1] * e1[s]);
                c[0] *= e0[s];
            }
            float Z = 0.0f;
#pragma unroll
            for (int j = 1; j <= NS; j++) Z += c[j];
            float invZ = __fdividef(1.0f, Z);

            float* __restrict__ onum = out + OFF_NUM + (size_t)pair * NS;
#pragma unroll
            for (int n = 0; n < NS; n++) onum[n] = c[n + 1] * invZ;
        }
    } else if (role == 1) {
        attr_split<5, 3>(typ, exist, b, lane, out, OFF_TYPE, OFF_NTYPE, OFF_RTYPE);
    } else if (role == 2) {
        attr_split<6, 3>(siz, exist, b, lane, out, OFF_SIZE, OFF_NSIZE, OFF_RSIZE);
    } else if (role == 3) {
        color_q<true>(col, exist, b, lane, out);
    } else {
        color_q<false>(col, exist, b, lane, out);
    }
}

extern "C" void kernel_launch(void* const* d_in, const int* in_sizes, int n_in,
                              void* d_out, int out_size)
{
    const float* exist = (const float*)d_in[0];
    const float* typ   = (const float*)d_in[1];
    const float* siz   = (const float*)d_in[2];
    const float* col   = (const float*)d_in[3];
    float* out = (float*)d_out;

    // 128 blocks × 320 threads: single wave on 148 SMs, 10 role warps/block.
    scene_engine_kernel<<<128, 320>>>(exist, typ, siz, col, out);
}